// round 14
// baseline (speedup 1.0000x reference)
#include <cuda_runtime.h>
#include <cuda_fp16.h>
#include <math.h>
#include <stdint.h>

constexpr int cB = 2, cS = 1024, cD = 512, cH = 32, cF = 2048, cC = 1000, cL = 2;
constexpr int LUTN = 63, LUTSZ = LUTN * LUTN;

// ---------------------------------------------------------------------------
// Scratch
// ---------------------------------------------------------------------------
__device__ float  g_x[cB * cS * cD];
__device__ __half g_xh[cB * cS * cD];
__device__ __half g_Qh[cB * cS * cD];
__device__ __half g_Kh[cB * cS * cD];
__device__ __half g_Vh[cB * cS * cD];
__device__ float  g_scores[cB * cS * cS];
__device__ __half g_probs[cB * cS * cS];
__device__ float  g_blut[cL * LUTSZ];
__device__ float  g_tmp[cB * cS * cD];
__device__ __half g_Hh[cB * cS * cF];
__device__ float  g_pooled[cB * cD];
__device__ __half g_wq[cL * cD * cD];
__device__ __half g_wk[cL * cD * cD];
__device__ __half g_wv[cL * cD * cD];
__device__ __half g_f1[cL * cD * cF];
__device__ __half g_f2[cL * cF * cD];

// ---------------------------------------------------------------------------
// Reductions
// ---------------------------------------------------------------------------
__device__ __forceinline__ float warpSum(float v) {
#pragma unroll
    for (int o = 16; o > 0; o >>= 1) v += __shfl_xor_sync(0xffffffffu, v, o);
    return v;
}
__device__ __forceinline__ float warpMax(float v) {
#pragma unroll
    for (int o = 16; o > 0; o >>= 1) v = fmaxf(v, __shfl_xor_sync(0xffffffffu, v, o));
    return v;
}

// ---------------------------------------------------------------------------
// fp16 GEMM, m16n8k16, fp32 accumulate. 256 threads, 4x2 warp grid.
// CTA tile (64*MT) x 64; warp tile (16*MT) x 32.
// 8 warps/CTA x 2 CTAs/SM = 16 warps/SM: doubles latency hiding vs the
// 128-thread version whose 4-warp CTAs left ~1000 exposed cycles/iter
// (R13 profile: occ 10.5%, tensor 23%).
// NT=true : B is [N, K] row-major, non-trans ldmatrix.
// NT=false: B is [K, N] row-major, ldmatrix.trans.
// EPI: 0 plain | 1 +bias+relu | 2 +bias | 3 *scale + LUT-bias (scores)
// OUTH: half output. FUSE3: QKV sharing A. Batched via grid.z strides.
// ---------------------------------------------------------------------------
constexpr int TBK  = 32;   // halfs per k-tile
constexpr int HSTR = 40;   // A / NT-B smem row stride (halfs)
constexpr int STG  = 3;
constexpr int WNT  = 4;    // fixed: TN = 64

__device__ __forceinline__ void cpa16(uint32_t dst, const void* src) {
    asm volatile("cp.async.cg.shared.global [%0], [%1], 16;\n" :: "r"(dst), "l"(src));
}
__device__ __forceinline__ void ldm4(uint32_t addr, uint32_t& r0, uint32_t& r1,
                                     uint32_t& r2, uint32_t& r3) {
    asm volatile("ldmatrix.sync.aligned.m8n8.x4.shared.b16 {%0,%1,%2,%3}, [%4];"
                 : "=r"(r0), "=r"(r1), "=r"(r2), "=r"(r3) : "r"(addr));
}
__device__ __forceinline__ void ldm4t(uint32_t addr, uint32_t& r0, uint32_t& r1,
                                      uint32_t& r2, uint32_t& r3) {
    asm volatile("ldmatrix.sync.aligned.m8n8.x4.trans.shared.b16 {%0,%1,%2,%3}, [%4];"
                 : "=r"(r0), "=r"(r1), "=r"(r2), "=r"(r3) : "r"(addr));
}
__device__ __forceinline__ void mma_f16(float c[4], const uint32_t a[4], const uint32_t b[2]) {
    asm volatile(
        "mma.sync.aligned.m16n8k16.row.col.f32.f16.f16.f32 "
        "{%0,%1,%2,%3}, {%4,%5,%6,%7}, {%8,%9}, {%0,%1,%2,%3};"
        : "+f"(c[0]), "+f"(c[1]), "+f"(c[2]), "+f"(c[3])
        : "r"(a[0]), "r"(a[1]), "r"(a[2]), "r"(a[3]), "r"(b[0]), "r"(b[1]));
}

constexpr int hSmemBytes(int MT, bool NT) {
    const int TN = 16 * WNT;            // 64
    const int ab = (64 * MT) * HSTR * 2;
    const int bb = NT ? TN * HSTR * 2 : TBK * (TN + 8) * 2;
    return STG * (ab + bb);
}

template <int MT, bool NT, int EPI, bool OUTH, bool FUSE3>
__global__ __launch_bounds__(256, 2) void hgemm_kernel(
    const __half* __restrict__ A, const __half* __restrict__ Bm, void* Cm_,
    const __half* __restrict__ B1, void* C1_,
    const __half* __restrict__ B2, void* C2_,
    int M, int N, int K, int sA, int sB, int sC, int nb,
    const float* __restrict__ biasv, const float* __restrict__ lutOrBias, float scalev)
{
    constexpr int TM = 64 * MT;
    constexpr int TN = 16 * WNT;        // 64
    constexpr int BSTRh = NT ? HSTR : (TN + 8);
    constexpr int ABYTES = TM * HSTR * 2;
    constexpr int BBYTES = NT ? TN * HSTR * 2 : TBK * BSTRh * 2;

    extern __shared__ __half smem[];
    const uint32_t sbase = (uint32_t)__cvta_generic_to_shared(smem);
    const uint32_t aBase = sbase;
    const uint32_t bBase = sbase + STG * ABYTES;

    A  += (size_t)blockIdx.z * sA;
    Bm += (size_t)blockIdx.z * sB;
    char* Cme = (char*)Cm_ + (size_t)blockIdx.z * sC * (OUTH ? 2 : 4);

    int bx = blockIdx.x;
    if (FUSE3) {
        const int mat = bx / nb;
        bx -= mat * nb;
        if (mat == 1) { Bm = B1; Cme = (char*)C1_; }
        else if (mat == 2) { Bm = B2; Cme = (char*)C2_; }
    }
    const int bm0 = blockIdx.y * TM;
    const int bn0 = bx * TN;

    const int t = threadIdx.x;
    const int lane = t & 31, w = t >> 5;
    const int gid = lane >> 2, tidg = lane & 3;
    const int wm0 = (w & 3) * (16 * MT);     // 4 M-warps
    const int wn0 = (w >> 2) * (8 * WNT);    // 2 N-warps

    const int aRow = (lane & 15);
    const int aKB  = ((lane >> 4) & 1) * 16;
    const int bRow = (lane & 7) + ((lane >> 4) & 1) * 8;
    const int bKB  = ((lane >> 3) & 1) * 16;
    const int bRowT = ((lane >> 3) & 1) * 8 + (lane & 7);
    const int bColT = (lane >> 4) * 8;

    auto load_stage = [&](int st, int k0) {
        const uint32_t ab = aBase + st * ABYTES;
#pragma unroll
        for (int i = 0; i < (TM * 4) / 256; i++) {
            const int idx = t + i * 256;
            const int row = idx >> 2, c16 = idx & 3;
            cpa16(ab + row * (HSTR * 2) + c16 * 16, A + (size_t)(bm0 + row) * K + k0 + c16 * 8);
        }
        const uint32_t bb = bBase + st * BBYTES;
        if (NT) {
            // TN*4 = 256 items
            const int row = t >> 2, c16 = t & 3;
            cpa16(bb + row * (HSTR * 2) + c16 * 16, Bm + (size_t)(bn0 + row) * K + k0 + c16 * 8);
        } else {
            // TBK * TN/8 = 256 items
            constexpr int perRow = TN / 8;
            const int kk = t / perRow, ch = t % perRow;
            cpa16(bb + kk * (BSTRh * 2) + ch * 16, Bm + (size_t)(k0 + kk) * N + bn0 + ch * 8);
        }
    };

    float acc[MT][WNT][4] = {};
    const int nk = K / TBK;

    load_stage(0, 0);
    asm volatile("cp.async.commit_group;" ::: "memory");
    load_stage(1, TBK);
    asm volatile("cp.async.commit_group;" ::: "memory");

    for (int it = 0; it < nk; it++) {
        asm volatile("cp.async.wait_group 1;" ::: "memory");
        __syncthreads();
        const int nxt = it + 2;
        if (nxt < nk) load_stage(nxt % STG, nxt * TBK);
        asm volatile("cp.async.commit_group;" ::: "memory");

        const int st = it % STG;
        const uint32_t aLane = aBase + st * ABYTES + (wm0 + aRow) * (HSTR * 2) + aKB;
        const uint32_t bST   = bBase + st * BBYTES;

#pragma unroll
        for (int ks = 0; ks < 2; ks++) {
            uint32_t a[MT][4], b[WNT][2];
#pragma unroll
            for (int mt = 0; mt < MT; mt++)
                ldm4(aLane + mt * (16 * HSTR * 2) + ks * 32,
                     a[mt][0], a[mt][1], a[mt][2], a[mt][3]);
#pragma unroll
            for (int np = 0; np < WNT / 2; np++) {
                uint32_t r0, r1, r2, r3;
                if (NT) {
                    const uint32_t addr = bST + (wn0 + np * 16 + bRow) * (HSTR * 2) + ks * 32 + bKB;
                    ldm4(addr, r0, r1, r2, r3);
                } else {
                    const uint32_t addr = bST + (ks * 16 + bRowT) * (BSTRh * 2)
                                        + (wn0 + np * 16 + bColT) * 2;
                    ldm4t(addr, r0, r1, r2, r3);
                }
                b[2 * np][0] = r0; b[2 * np][1] = r1;
                b[2 * np + 1][0] = r2; b[2 * np + 1][1] = r3;
            }
#pragma unroll
            for (int mt = 0; mt < MT; mt++)
#pragma unroll
                for (int nt = 0; nt < WNT; nt++)
                    mma_f16(acc[mt][nt], a[mt], b[nt]);
        }
    }

#pragma unroll
    for (int mt = 0; mt < MT; mt++) {
#pragma unroll
        for (int nt = 0; nt < WNT; nt++) {
            const int row = bm0 + wm0 + mt * 16 + gid;
            const int col = bn0 + wn0 + nt * 8 + tidg * 2;
#pragma unroll
            for (int h = 0; h < 2; h++) {
                const int r = row + h * 8;
                float vx = acc[mt][nt][h * 2], vy = acc[mt][nt][h * 2 + 1];
                if (EPI == 1 || EPI == 2) {
                    vx += biasv[col]; vy += biasv[col + 1];
                    if (EPI == 1) { vx = fmaxf(vx, 0.f); vy = fmaxf(vy, 0.f); }
                }
                if (EPI == 3) {
                    const int ix = r >> 5, iy = r & 31;
                    const int a0 = ((col)     >> 5) - ix + 31, b0 = ((col)     & 31) - iy + 31;
                    const int a1 = ((col + 1) >> 5) - ix + 31, b1 = ((col + 1) & 31) - iy + 31;
                    vx = vx * scalev + __ldg(lutOrBias + a0 * LUTN + b0);
                    vy = vy * scalev + __ldg(lutOrBias + a1 * LUTN + b1);
                }
                if (OUTH) {
                    *(__half2*)((__half*)Cme + (size_t)r * N + col) = __floats2half2_rn(vx, vy);
                } else {
                    *(float2*)((float*)Cme + (size_t)r * N + col) = make_float2(vx, vy);
                }
            }
        }
    }
}

// ---------------------------------------------------------------------------
// Fused prep (unchanged)
// ---------------------------------------------------------------------------
constexpr int N1 = cL * cD * cD / 4;
constexpr int N2 = cL * cD * cF / 4;
constexpr int NX = cB * cS * cD / 4;
constexpr int NO = (cB * cC) / 4;
constexpr int NP = (cB * cD) / 4;
constexpr int S0 = N1, S1 = 2 * N1, S2 = 3 * N1;
constexpr int S3 = S2 + N2, S4 = S3 + N2, S5 = S4 + NX, S6 = S5 + NO, S7 = S6 + NP;

__device__ __forceinline__ void cvt4(const float* s, __half* d, int i) {
    float4 v = ((const float4*)s)[i];
    ((__half2*)d)[2 * i]     = __floats2half2_rn(v.x, v.y);
    ((__half2*)d)[2 * i + 1] = __floats2half2_rn(v.z, v.w);
}

__global__ __launch_bounds__(256) void prep_kernel(
    const float* __restrict__ Wq, const float* __restrict__ Wk, const float* __restrict__ Wv,
    const float* __restrict__ f1, const float* __restrict__ f2,
    const float* __restrict__ x,  const float* __restrict__ fcb,
    __half* gwq, __half* gwk, __half* gwv, __half* gf1, __half* gf2,
    float* gx, __half* gxh, float* outp, float* pooled)
{
    const int i = blockIdx.x * 256 + threadIdx.x;
    if (i < S0)      cvt4(Wq, gwq, i);
    else if (i < S1) cvt4(Wk, gwk, i - S0);
    else if (i < S2) cvt4(Wv, gwv, i - S1);
    else if (i < S3) cvt4(f1, gf1, i - S2);
    else if (i < S4) cvt4(f2, gf2, i - S3);
    else if (i < S5) {
        const int j = i - S4;
        float4 v = ((const float4*)x)[j];
        ((float4*)gx)[j] = v;
        ((__half2*)gxh)[2 * j]     = __floats2half2_rn(v.x, v.y);
        ((__half2*)gxh)[2 * j + 1] = __floats2half2_rn(v.z, v.w);
    } else if (i < S6) {
        const int j = i - S5;
#pragma unroll
        for (int q = 0; q < 4; q++) {
            const int e = j * 4 + q;
            outp[e] = fcb[e % cC];
        }
    } else if (i < S7) {
        ((float4*)pooled)[i - S6] = make_float4(0.f, 0.f, 0.f, 0.f);
    }
}

// ---------------------------------------------------------------------------
// Pair-bias LUT (unchanged)
// ---------------------------------------------------------------------------
__global__ __launch_bounds__(256) void biaslut_kernel(
    const float* __restrict__ coords,
    const float* __restrict__ rw1, const float* __restrict__ rb1,
    const float* __restrict__ rw2, const float* __restrict__ rb2,
    const float* __restrict__ tw1, const float* __restrict__ tb1,
    const float* __restrict__ tw2, const float* __restrict__ tb2,
    const float* __restrict__ fw1, const float* __restrict__ fb1,
    const float* __restrict__ fw2, const float* __restrict__ fb2,
    float* __restrict__ lut)
{
    const int l = blockIdx.y;
    __shared__ float s_rw1[3 * cH], s_rb1[cH], s_rw2[cH];
    __shared__ float s_tw1[2 * cH], s_tb1[cH], s_tw2[cH];
    __shared__ float s_fw1[4 * cH], s_fb1[cH], s_fw2[cH];
    const int t = threadIdx.x;
    if (t < 3 * cH) s_rw1[t] = rw1[l * 3 * cH + t];
    if (t < 2 * cH) s_tw1[t] = tw1[l * 2 * cH + t];
    if (t < 4 * cH) s_fw1[t] = fw1[l * 4 * cH + t];
    if (t < cH) {
        s_rb1[t] = rb1[l * cH + t]; s_rw2[t] = rw2[l * cH + t];
        s_tb1[t] = tb1[l * cH + t]; s_tw2[t] = tw2[l * cH + t];
        s_fb1[t] = fb1[l * cH + t]; s_fw2[t] = fw2[l * cH + t];
    }
    __syncthreads();

    const int idx = blockIdx.x * 256 + t;
    if (idx >= LUTSZ) return;
    const int da = idx / LUTN - 31;
    const int db = idx % LUTN - 31;
    const float xa = coords[2 * (da < 0 ? -da : da) + 1];
    const float xb = coords[2 * (db < 0 ? -db : db) + 1];
    const float dx = (da < 0) ? -xa : xa;
    const float dy = (db < 0) ? -xb : xb;

    const float r2 = dx * dx + dy * dy;
    const float dist = sqrtf(r2 + 1e-8f);
    const float rinv = (r2 > 0.f) ? rsqrtf(r2) : 0.f;
    const float st = dy * rinv;
    const float ct = (r2 > 0.f) ? dx * rinv : 1.f;

    float acc = rb2[l] + tb2[l] + fb2[l];
#pragma unroll
    for (int h = 0; h < cH; h++) {
        float hr = fmaf(dist, s_rw1[h], fmaf(st, s_rw1[cH + h], fmaf(ct, s_rw1[2 * cH + h], s_rb1[h])));
        if (hr > 0.f) acc += hr * s_rw2[h];
        float ht = fmaf(dx, s_tw1[h], fmaf(dy, s_tw1[cH + h], s_tb1[h]));
        if (ht > 0.f) acc += ht * s_tw2[h];
        float hf = fmaf(dx, s_fw1[h] - s_fw1[2 * cH + h],
                    fmaf(dy, s_fw1[cH + h] - s_fw1[3 * cH + h], s_fb1[h]));
        if (hf > 0.f) acc += hf * s_fw2[h];
    }
    lut[l * LUTSZ + idx] = acc;
}

// ---------------------------------------------------------------------------
// Warp-per-row softmax / LN / pool / fc (unchanged)
// ---------------------------------------------------------------------------
__global__ __launch_bounds__(256) void softmax_kernel(
    const float* __restrict__ sc, __half* __restrict__ pr)
{
    const int row  = blockIdx.x * 8 + (threadIdx.x >> 5);
    const int lane = threadIdx.x & 31;
    const float4* p = (const float4*)(sc + (size_t)row * cS);
    uint2* ph = (uint2*)(pr + (size_t)row * cS);

    float4 v[8];
    float m = -3.0e38f;
#pragma unroll
    for (int k = 0; k < 8; k++) {
        v[k] = p[lane + k * 32];
        m = fmaxf(m, fmaxf(fmaxf(v[k].x, v[k].y), fmaxf(v[k].z, v[k].w)));
    }
    m = warpMax(m);
    float s = 0.f;
#pragma unroll
    for (int k = 0; k < 8; k++) {
        v[k].x = __expf(v[k].x - m); v[k].y = __expf(v[k].y - m);
        v[k].z = __expf(v[k].z - m); v[k].w = __expf(v[k].w - m);
        s += v[k].x + v[k].y + v[k].z + v[k].w;
    }
    s = warpSum(s);
    const float inv = 1.f / s;
#pragma unroll
    for (int k = 0; k < 8; k++) {
        __half2 h0 = __floats2half2_rn(v[k].x * inv, v[k].y * inv);
        __half2 h1 = __floats2half2_rn(v[k].z * inv, v[k].w * inv);
        uint2 u;
        u.x = *(uint32_t*)&h0; u.y = *(uint32_t*)&h1;
        ph[lane + k * 32] = u;
    }
}

__global__ __launch_bounds__(256) void ln_kernel(
    float* __restrict__ x, __half* __restrict__ xh, const float* __restrict__ add,
    const float* __restrict__ g, const float* __restrict__ b)
{
    const int row  = blockIdx.x * 8 + (threadIdx.x >> 5);
    const int lane = threadIdx.x & 31;
    float4* px = (float4*)(x + (size_t)row * cD);

    float4 v[4];
    float s = 0.f, s2 = 0.f;
#pragma unroll
    for (int k = 0; k < 4; k++) {
        v[k] = px[lane + k * 32];
        if (add) {
            float4 a4 = ((const float4*)(add + (size_t)row * cD))[lane + k * 32];
            v[k].x += a4.x; v[k].y += a4.y; v[k].z += a4.z; v[k].w += a4.w;
        }
        s  += v[k].x + v[k].y + v[k].z + v[k].w;
        s2 += v[k].x * v[k].x + v[k].y * v[k].y + v[k].z * v[k].z + v[k].w * v[k].w;
    }
    s = warpSum(s); s2 = warpSum(s2);
    const float mu = s * (1.f / cD);
    const float var = fmaxf(s2 * (1.f / cD) - mu * mu, 0.f);
    const float rs = rsqrtf(var + 1e-5f);
#pragma unroll
    for (int k = 0; k < 4; k++) {
        const int e = (lane + k * 32) * 4;
        float4 g4 = ((const float4*)g)[lane + k * 32];
        float4 b4 = ((const float4*)b)[lane + k * 32];
        float4 o;
        o.x = (v[k].x - mu) * rs * g4.x + b4.x;
        o.y = (v[k].y - mu) * rs * g4.y + b4.y;
        o.z = (v[k].z - mu) * rs * g4.z + b4.z;
        o.w = (v[k].w - mu) * rs * g4.w + b4.w;
        px[lane + k * 32] = o;
        if (xh) {
            __half2 h0 = __floats2half2_rn(o.x, o.y);
            __half2 h1 = __floats2half2_rn(o.z, o.w);
            uint2 u; u.x = *(uint32_t*)&h0; u.y = *(uint32_t*)&h1;
            *(uint2*)(xh + (size_t)row * cD + e) = u;
        }
    }
}

__global__ __launch_bounds__(256) void pool_kernel(const float* __restrict__ x, float* __restrict__ outp) {
    const int b = blockIdx.y;
    const int s0 = blockIdx.x * 64;
    const int d = threadIdx.x * 2;
    float2 acc = make_float2(0.f, 0.f);
    const float* p = x + ((size_t)b * cS + s0) * cD + d;
#pragma unroll 8
    for (int i = 0; i < 64; i++) {
        float2 val = *(const float2*)(p + (size_t)i * cD);
        acc.x += val.x; acc.y += val.y;
    }
    atomicAdd(&outp[b * cD + d],     acc.x * (1.f / cS));
    atomicAdd(&outp[b * cD + d + 1], acc.y * (1.f / cS));
}

__global__ __launch_bounds__(256) void fc_kernel(
    const float* __restrict__ pooled, const float* __restrict__ w,
    float* __restrict__ outc)
{
    const int idx = blockIdx.x * 256 + threadIdx.x;
    if (idx >= cB * cC) return;
    const int b = idx / cC, c = idx % cC;
    const int d0 = blockIdx.y * 128;
    const float* pp = pooled + b * cD + d0;
    const float* wp = w + (size_t)d0 * cC + c;
    float s = 0.f;
#pragma unroll 8
    for (int d = 0; d < 128; d++) s += pp[d] * wp[(size_t)d * cC];
    atomicAdd(&outc[idx], s);
}

// ---------------------------------------------------------------------------
// Launch
// ---------------------------------------------------------------------------
extern "C" void kernel_launch(void* const* d_in, const int* in_sizes, int n_in,
                              void* d_out, int out_size)
{
    const float* x      = (const float*)d_in[0];
    const float* coords = (const float*)d_in[1];
    const float* Wq     = (const float*)d_in[2];
    const float* Wk     = (const float*)d_in[3];
    const float* Wv     = (const float*)d_in[4];
    const float* rw1 = (const float*)d_in[5],  *rb1 = (const float*)d_in[6];
    const float* rw2 = (const float*)d_in[7],  *rb2 = (const float*)d_in[8];
    const float* tw1 = (const float*)d_in[9],  *tb1 = (const float*)d_in[10];
    const float* tw2 = (const float*)d_in[11], *tb2 = (const float*)d_in[12];
    const float* fw1 = (const float*)d_in[13], *fb1 = (const float*)d_in[14];
    const float* fw2 = (const float*)d_in[15], *fb2 = (const float*)d_in[16];
    const float* ln1g = (const float*)d_in[17], *ln1b = (const float*)d_in[18];
    const float* ffw1 = (const float*)d_in[19], *ffb1 = (const float*)d_in[20];
    const float* ffw2 = (const float*)d_in[21], *ffb2 = (const float*)d_in[22];
    const float* ln2g = (const float*)d_in[23], *ln2b = (const float*)d_in[24];
    const float* lnfg = (const float*)d_in[25], *lnfb = (const float*)d_in[26];
    const float* fcw  = (const float*)d_in[27], *fcb  = (const float*)d_in[28];
    float* out = (float*)d_out;

    float *gx, *gS, *gLut, *gT, *gP;
    __half *gxh, *gQh, *gKh, *gVh, *gPr, *gHh, *gwq, *gwk, *gwv, *gf1, *gf2;
    cudaGetSymbolAddress((void**)&gx,   g_x);
    cudaGetSymbolAddress((void**)&gxh,  g_xh);
    cudaGetSymbolAddress((void**)&gQh,  g_Qh);
    cudaGetSymbolAddress((void**)&gKh,  g_Kh);
    cudaGetSymbolAddress((void**)&gVh,  g_Vh);
    cudaGetSymbolAddress((void**)&gS,   g_scores);
    cudaGetSymbolAddress((void**)&gPr,  g_probs);
    cudaGetSymbolAddress((void**)&gLut, g_blut);
    cudaGetSymbolAddress((void**)&gT,   g_tmp);
    cudaGetSymbolAddress((void**)&gHh,  g_Hh);
    cudaGetSymbolAddress((void**)&gP,   g_pooled);
    cudaGetSymbolAddress((void**)&gwq,  g_wq);
    cudaGetSymbolAddress((void**)&gwk,  g_wk);
    cudaGetSymbolAddress((void**)&gwv,  g_wv);
    cudaGetSymbolAddress((void**)&gf1,  g_f1);
    cudaGetSymbolAddress((void**)&gf2,  g_f2);

    const float invscale = 1.f / sqrtf((float)cD);
    const int BS = cB * cS;  // 2048

    constexpr int smNN2 = hSmemBytes(2, false);  // 128x64 NN: 44544
    constexpr int smNT2 = hSmemBytes(2, true);   // 128x64 NT: 46080
    constexpr int smNN1 = hSmemBytes(1, false);  // 64x64  NN: 29184
    cudaFuncSetAttribute(hgemm_kernel<2, false, 0, true,  true>,  cudaFuncAttributeMaxDynamicSharedMemorySize, smNN2);
    cudaFuncSetAttribute(hgemm_kernel<2, true,  3, false, false>, cudaFuncAttributeMaxDynamicSharedMemorySize, smNT2);
    cudaFuncSetAttribute(hgemm_kernel<1, false, 0, false, false>, cudaFuncAttributeMaxDynamicSharedMemorySize, smNN1);
    cudaFuncSetAttribute(hgemm_kernel<2, false, 1, true,  false>, cudaFuncAttributeMaxDynamicSharedMemorySize, smNN2);
    cudaFuncSetAttribute(hgemm_kernel<1, false, 2, false, false>, cudaFuncAttributeMaxDynamicSharedMemorySize, smNN1);

    prep_kernel<<<(S7 + 255) / 256, 256>>>(
        Wq, Wk, Wv, ffw1, ffw2, x, fcb,
        gwq, gwk, gwv, gf1, gf2, gx, gxh, out, gP);

    biaslut_kernel<<<dim3((LUTSZ + 255) / 256, cL), 256>>>(coords,
        rw1, rb1, rw2, rb2, tw1, tb1, tw2, tb2, fw1, fb1, fw2, fb2, gLut);

    for (int l = 0; l < cL; l++) {
        const size_t wo = (size_t)l * cD * cD;
        // Fused QKV: 128x64 tiles, 256 thr -> grid 24x16 = 384 CTAs
        hgemm_kernel<2, false, 0, true, true><<<dim3(3 * (cD / 64), BS / 128), 256, smNN2>>>(
            gxh, gwq + wo, gQh, gwk + wo, gKh, gwv + wo, gVh,
            BS, cD, cD, 0, 0, 0, cD / 64, nullptr, nullptr, 0.f);

        // scores: 128x64 tiles -> grid 16x8x2 = 256 CTAs
        hgemm_kernel<2, true, 3, false, false><<<dim3(cS / 64, cS / 128, cB), 256, smNT2>>>(
            gQh, gKh, gS, nullptr, nullptr, nullptr, nullptr,
            cS, cS, cD, cS * cD, cS * cD, cS * cS, 0,
            nullptr, gLut + (size_t)l * LUTSZ, invscale);

        softmax_kernel<<<BS / 8, 256>>>(gS, gPr);

        // attn_out: 64x64 tiles -> grid 8x16x2 = 256 CTAs
        hgemm_kernel<1, false, 0, false, false><<<dim3(cD / 64, cS / 64, cB), 256, smNN1>>>(
            gPr, gVh, gT, nullptr, nullptr, nullptr, nullptr,
            cS, cD, cS, cS * cS, cS * cD, cS * cD, 0, nullptr, nullptr, 0.f);

        ln_kernel<<<BS / 8, 256>>>(gx, gxh, gT, ln1g + l * cD, ln1b + l * cD);

        // FFN1: 128x64 tiles -> grid 32x16 = 512 CTAs
        hgemm_kernel<2, false, 1, true, false><<<dim3(cF / 64, BS / 128), 256, smNN2>>>(
            gxh, gf1 + (size_t)l * cD * cF, gHh, nullptr, nullptr, nullptr, nullptr,
            BS, cF, cD, 0, 0, 0, 0, ffb1 + l * cF, nullptr, 0.f);
        // FFN2: 64x64 tiles -> grid 8x32 = 256 CTAs
        hgemm_kernel<1, false, 2, false, false><<<dim3(cD / 64, BS / 64), 256, smNN1>>>(
            gHh, gf2 + (size_t)l * cF * cD, gT, nullptr, nullptr, nullptr, nullptr,
            BS, cD, cF, 0, 0, 0, 0, ffb2 + l * cD, nullptr, 0.f);

        ln_kernel<<<BS / 8, 256>>>(gx, gxh, gT, ln2g + l * cD, ln2b + l * cD);
    }

    ln_kernel<<<BS / 8, 256>>>(gx, nullptr, nullptr, lnfg, lnfb);
    pool_kernel<<<dim3(cS / 64, cB), 256>>>(gx, gP);
    fc_kernel<<<dim3((cB * cC + 255) / 256, cD / 128), 256>>>(gP, fcw, out);
}

// round 15
// speedup vs baseline: 1.0592x; 1.0592x over previous
#include <cuda_runtime.h>
#include <cuda_fp16.h>
#include <math.h>
#include <stdint.h>

constexpr int cB = 2, cS = 1024, cD = 512, cH = 32, cF = 2048, cC = 1000, cL = 2;
constexpr int LUTN = 63, LUTSZ = LUTN * LUTN;

// ---------------------------------------------------------------------------
// Scratch
// ---------------------------------------------------------------------------
__device__ float  g_x[cB * cS * cD];
__device__ __half g_xh[cB * cS * cD];
__device__ __half g_Qh[cB * cS * cD];
__device__ __half g_Kh[cB * cS * cD];
__device__ __half g_Vh[cB * cS * cD];
__device__ float  g_scores[cB * cS * cS];
__device__ __half g_probs[cB * cS * cS];
__device__ float  g_blut[cL * LUTSZ];
__device__ float  g_tmp[cB * cS * cD];
__device__ __half g_Hh[cB * cS * cF];
__device__ float  g_pooled[cB * cD];
__device__ __half g_wq[cL * cD * cD];
__device__ __half g_wk[cL * cD * cD];
__device__ __half g_wv[cL * cD * cD];
__device__ __half g_f1[cL * cD * cF];
__device__ __half g_f2[cL * cF * cD];

// ---------------------------------------------------------------------------
// Reductions
// ---------------------------------------------------------------------------
__device__ __forceinline__ float warpSum(float v) {
#pragma unroll
    for (int o = 16; o > 0; o >>= 1) v += __shfl_xor_sync(0xffffffffu, v, o);
    return v;
}
__device__ __forceinline__ float warpMax(float v) {
#pragma unroll
    for (int o = 16; o > 0; o >>= 1) v = fmaxf(v, __shfl_xor_sync(0xffffffffu, v, o));
    return v;
}

// ---------------------------------------------------------------------------
// fp16 GEMM, m16n8k16, fp32 accumulate. 128 threads (4 warps, 2x2 warp grid).
// CTA tile (32*MT) x (16*WNT); warp tile (16*MT) x (8*WNT).
// Crossbar-bound analysis (R14 falsified the latency theory): tensor %
// scales with warp-tile AREA (HMMA per LDSM byte). Big tiles (64x64 warp,
// MT=4/WNT=8, ratio 4) where the grid allows a full single wave
// (QKV 192 CTAs, FFN1 256); R13 shapes elsewhere.
// MAXB: blocks/SM for launch_bounds (2 for big tiles: acc=128 regs).
// NT=true : B is [N, K] row-major, non-trans ldmatrix.
// NT=false: B is [K, N] row-major, ldmatrix.trans.
// EPI: 0 plain | 1 +bias+relu | 2 +bias | 3 *scale + LUT-bias (scores)
// OUTH: half output. FUSE3: QKV sharing A. Batched via grid.z strides.
// ---------------------------------------------------------------------------
constexpr int TBK  = 32;
constexpr int HSTR = 40;
constexpr int STG  = 3;

__device__ __forceinline__ void cpa16(uint32_t dst, const void* src) {
    asm volatile("cp.async.cg.shared.global [%0], [%1], 16;\n" :: "r"(dst), "l"(src));
}
__device__ __forceinline__ void ldm4(uint32_t addr, uint32_t& r0, uint32_t& r1,
                                     uint32_t& r2, uint32_t& r3) {
    asm volatile("ldmatrix.sync.aligned.m8n8.x4.shared.b16 {%0,%1,%2,%3}, [%4];"
                 : "=r"(r0), "=r"(r1), "=r"(r2), "=r"(r3) : "r"(addr));
}
__device__ __forceinline__ void ldm4t(uint32_t addr, uint32_t& r0, uint32_t& r1,
                                      uint32_t& r2, uint32_t& r3) {
    asm volatile("ldmatrix.sync.aligned.m8n8.x4.trans.shared.b16 {%0,%1,%2,%3}, [%4];"
                 : "=r"(r0), "=r"(r1), "=r"(r2), "=r"(r3) : "r"(addr));
}
__device__ __forceinline__ void mma_f16(float c[4], const uint32_t a[4], const uint32_t b[2]) {
    asm volatile(
        "mma.sync.aligned.m16n8k16.row.col.f32.f16.f16.f32 "
        "{%0,%1,%2,%3}, {%4,%5,%6,%7}, {%8,%9}, {%0,%1,%2,%3};"
        : "+f"(c[0]), "+f"(c[1]), "+f"(c[2]), "+f"(c[3])
        : "r"(a[0]), "r"(a[1]), "r"(a[2]), "r"(a[3]), "r"(b[0]), "r"(b[1]));
}

constexpr int hSmemBytes(int MT, int WNT, bool NT) {
    const int TN = 16 * WNT;
    const int ab = (32 * MT) * HSTR * 2;
    const int bb = NT ? TN * HSTR * 2 : TBK * (TN + 8) * 2;
    return STG * (ab + bb);
}

template <int MT, int WNT, int MAXB, bool NT, int EPI, bool OUTH, bool FUSE3>
__global__ __launch_bounds__(128, MAXB) void hgemm_kernel(
    const __half* __restrict__ A, const __half* __restrict__ Bm, void* Cm_,
    const __half* __restrict__ B1, void* C1_,
    const __half* __restrict__ B2, void* C2_,
    int M, int N, int K, int sA, int sB, int sC, int nb,
    const float* __restrict__ biasv, const float* __restrict__ lutOrBias, float scalev)
{
    constexpr int TM = 32 * MT;
    constexpr int TN = 16 * WNT;
    constexpr int BSTRh = NT ? HSTR : (TN + 8);
    constexpr int ABYTES = TM * HSTR * 2;
    constexpr int BBYTES = NT ? TN * HSTR * 2 : TBK * BSTRh * 2;

    extern __shared__ __half smem[];
    const uint32_t sbase = (uint32_t)__cvta_generic_to_shared(smem);
    const uint32_t aBase = sbase;
    const uint32_t bBase = sbase + STG * ABYTES;

    A  += (size_t)blockIdx.z * sA;
    Bm += (size_t)blockIdx.z * sB;
    char* Cme = (char*)Cm_ + (size_t)blockIdx.z * sC * (OUTH ? 2 : 4);

    int bx = blockIdx.x;
    if (FUSE3) {
        const int mat = bx / nb;
        bx -= mat * nb;
        if (mat == 1) { Bm = B1; Cme = (char*)C1_; }
        else if (mat == 2) { Bm = B2; Cme = (char*)C2_; }
    }
    const int bm0 = blockIdx.y * TM;
    const int bn0 = bx * TN;

    const int t = threadIdx.x;
    const int lane = t & 31, w = t >> 5;
    const int gid = lane >> 2, tidg = lane & 3;
    const int wm0 = (w & 1) * (16 * MT);
    const int wn0 = (w >> 1) * (8 * WNT);

    const int aRow = (lane & 15);
    const int aKB  = ((lane >> 4) & 1) * 16;
    const int bRow = (lane & 7) + ((lane >> 4) & 1) * 8;
    const int bKB  = ((lane >> 3) & 1) * 16;
    const int bRowT = ((lane >> 3) & 1) * 8 + (lane & 7);
    const int bColT = (lane >> 4) * 8;

    auto load_stage = [&](int st, int k0) {
        const uint32_t ab = aBase + st * ABYTES;
#pragma unroll
        for (int i = 0; i < MT; i++) {
            const int idx = t + i * 128;
            const int row = idx >> 2, c16 = idx & 3;
            cpa16(ab + row * (HSTR * 2) + c16 * 16, A + (size_t)(bm0 + row) * K + k0 + c16 * 8);
        }
        const uint32_t bb = bBase + st * BBYTES;
        if (NT) {
#pragma unroll
            for (int i = 0; i < TN / 32; i++) {
                const int idx = t + i * 128;
                const int row = idx >> 2, c16 = idx & 3;
                cpa16(bb + row * (HSTR * 2) + c16 * 16, Bm + (size_t)(bn0 + row) * K + k0 + c16 * 8);
            }
        } else {
            constexpr int perRow = TN / 8;
#pragma unroll
            for (int i = 0; i < (TBK * perRow) / 128; i++) {
                const int idx = t + i * 128;
                const int kk = idx / perRow, ch = idx % perRow;
                cpa16(bb + kk * (BSTRh * 2) + ch * 16, Bm + (size_t)(k0 + kk) * N + bn0 + ch * 8);
            }
        }
    };

    float acc[MT][WNT][4] = {};
    const int nk = K / TBK;

    load_stage(0, 0);
    asm volatile("cp.async.commit_group;" ::: "memory");
    load_stage(1, TBK);
    asm volatile("cp.async.commit_group;" ::: "memory");

    for (int it = 0; it < nk; it++) {
        asm volatile("cp.async.wait_group 1;" ::: "memory");
        __syncthreads();
        const int nxt = it + 2;
        if (nxt < nk) load_stage(nxt % STG, nxt * TBK);
        asm volatile("cp.async.commit_group;" ::: "memory");

        const int st = it % STG;
        const uint32_t aLane = aBase + st * ABYTES + (wm0 + aRow) * (HSTR * 2) + aKB;
        const uint32_t bST   = bBase + st * BBYTES;

#pragma unroll
        for (int ks = 0; ks < 2; ks++) {
            uint32_t a[MT][4], b[WNT][2];
#pragma unroll
            for (int mt = 0; mt < MT; mt++)
                ldm4(aLane + mt * (16 * HSTR * 2) + ks * 32,
                     a[mt][0], a[mt][1], a[mt][2], a[mt][3]);
#pragma unroll
            for (int np = 0; np < WNT / 2; np++) {
                uint32_t r0, r1, r2, r3;
                if (NT) {
                    const uint32_t addr = bST + (wn0 + np * 16 + bRow) * (HSTR * 2) + ks * 32 + bKB;
                    ldm4(addr, r0, r1, r2, r3);
                } else {
                    const uint32_t addr = bST + (ks * 16 + bRowT) * (BSTRh * 2)
                                        + (wn0 + np * 16 + bColT) * 2;
                    ldm4t(addr, r0, r1, r2, r3);
                }
                b[2 * np][0] = r0; b[2 * np][1] = r1;
                b[2 * np + 1][0] = r2; b[2 * np + 1][1] = r3;
            }
#pragma unroll
            for (int mt = 0; mt < MT; mt++)
#pragma unroll
                for (int nt = 0; nt < WNT; nt++)
                    mma_f16(acc[mt][nt], a[mt], b[nt]);
        }
    }

#pragma unroll
    for (int mt = 0; mt < MT; mt++) {
#pragma unroll
        for (int nt = 0; nt < WNT; nt++) {
            const int row = bm0 + wm0 + mt * 16 + gid;
            const int col = bn0 + wn0 + nt * 8 + tidg * 2;
#pragma unroll
            for (int h = 0; h < 2; h++) {
                const int r = row + h * 8;
                float vx = acc[mt][nt][h * 2], vy = acc[mt][nt][h * 2 + 1];
                if (EPI == 1 || EPI == 2) {
                    vx += biasv[col]; vy += biasv[col + 1];
                    if (EPI == 1) { vx = fmaxf(vx, 0.f); vy = fmaxf(vy, 0.f); }
                }
                if (EPI == 3) {
                    const int ix = r >> 5, iy = r & 31;
                    const int a0 = ((col)     >> 5) - ix + 31, b0 = ((col)     & 31) - iy + 31;
                    const int a1 = ((col + 1) >> 5) - ix + 31, b1 = ((col + 1) & 31) - iy + 31;
                    vx = vx * scalev + __ldg(lutOrBias + a0 * LUTN + b0);
                    vy = vy * scalev + __ldg(lutOrBias + a1 * LUTN + b1);
                }
                if (OUTH) {
                    *(__half2*)((__half*)Cme + (size_t)r * N + col) = __floats2half2_rn(vx, vy);
                } else {
                    *(float2*)((float*)Cme + (size_t)r * N + col) = make_float2(vx, vy);
                }
            }
        }
    }
}

// ---------------------------------------------------------------------------
// Fused prep (unchanged)
// ---------------------------------------------------------------------------
constexpr int N1 = cL * cD * cD / 4;
constexpr int N2 = cL * cD * cF / 4;
constexpr int NX = cB * cS * cD / 4;
constexpr int NO = (cB * cC) / 4;
constexpr int NP = (cB * cD) / 4;
constexpr int S0 = N1, S1 = 2 * N1, S2 = 3 * N1;
constexpr int S3 = S2 + N2, S4 = S3 + N2, S5 = S4 + NX, S6 = S5 + NO, S7 = S6 + NP;

__device__ __forceinline__ void cvt4(const float* s, __half* d, int i) {
    float4 v = ((const float4*)s)[i];
    ((__half2*)d)[2 * i]     = __floats2half2_rn(v.x, v.y);
    ((__half2*)d)[2 * i + 1] = __floats2half2_rn(v.z, v.w);
}

__global__ __launch_bounds__(256) void prep_kernel(
    const float* __restrict__ Wq, const float* __restrict__ Wk, const float* __restrict__ Wv,
    const float* __restrict__ f1, const float* __restrict__ f2,
    const float* __restrict__ x,  const float* __restrict__ fcb,
    __half* gwq, __half* gwk, __half* gwv, __half* gf1, __half* gf2,
    float* gx, __half* gxh, float* outp, float* pooled)
{
    const int i = blockIdx.x * 256 + threadIdx.x;
    if (i < S0)      cvt4(Wq, gwq, i);
    else if (i < S1) cvt4(Wk, gwk, i - S0);
    else if (i < S2) cvt4(Wv, gwv, i - S1);
    else if (i < S3) cvt4(f1, gf1, i - S2);
    else if (i < S4) cvt4(f2, gf2, i - S3);
    else if (i < S5) {
        const int j = i - S4;
        float4 v = ((const float4*)x)[j];
        ((float4*)gx)[j] = v;
        ((__half2*)gxh)[2 * j]     = __floats2half2_rn(v.x, v.y);
        ((__half2*)gxh)[2 * j + 1] = __floats2half2_rn(v.z, v.w);
    } else if (i < S6) {
        const int j = i - S5;
#pragma unroll
        for (int q = 0; q < 4; q++) {
            const int e = j * 4 + q;
            outp[e] = fcb[e % cC];
        }
    } else if (i < S7) {
        ((float4*)pooled)[i - S6] = make_float4(0.f, 0.f, 0.f, 0.f);
    }
}

// ---------------------------------------------------------------------------
// Pair-bias LUT (unchanged)
// ---------------------------------------------------------------------------
__global__ __launch_bounds__(256) void biaslut_kernel(
    const float* __restrict__ coords,
    const float* __restrict__ rw1, const float* __restrict__ rb1,
    const float* __restrict__ rw2, const float* __restrict__ rb2,
    const float* __restrict__ tw1, const float* __restrict__ tb1,
    const float* __restrict__ tw2, const float* __restrict__ tb2,
    const float* __restrict__ fw1, const float* __restrict__ fb1,
    const float* __restrict__ fw2, const float* __restrict__ fb2,
    float* __restrict__ lut)
{
    const int l = blockIdx.y;
    __shared__ float s_rw1[3 * cH], s_rb1[cH], s_rw2[cH];
    __shared__ float s_tw1[2 * cH], s_tb1[cH], s_tw2[cH];
    __shared__ float s_fw1[4 * cH], s_fb1[cH], s_fw2[cH];
    const int t = threadIdx.x;
    if (t < 3 * cH) s_rw1[t] = rw1[l * 3 * cH + t];
    if (t < 2 * cH) s_tw1[t] = tw1[l * 2 * cH + t];
    if (t < 4 * cH) s_fw1[t] = fw1[l * 4 * cH + t];
    if (t < cH) {
        s_rb1[t] = rb1[l * cH + t]; s_rw2[t] = rw2[l * cH + t];
        s_tb1[t] = tb1[l * cH + t]; s_tw2[t] = tw2[l * cH + t];
        s_fb1[t] = fb1[l * cH + t]; s_fw2[t] = fw2[l * cH + t];
    }
    __syncthreads();

    const int idx = blockIdx.x * 256 + t;
    if (idx >= LUTSZ) return;
    const int da = idx / LUTN - 31;
    const int db = idx % LUTN - 31;
    const float xa = coords[2 * (da < 0 ? -da : da) + 1];
    const float xb = coords[2 * (db < 0 ? -db : db) + 1];
    const float dx = (da < 0) ? -xa : xa;
    const float dy = (db < 0) ? -xb : xb;

    const float r2 = dx * dx + dy * dy;
    const float dist = sqrtf(r2 + 1e-8f);
    const float rinv = (r2 > 0.f) ? rsqrtf(r2) : 0.f;
    const float st = dy * rinv;
    const float ct = (r2 > 0.f) ? dx * rinv : 1.f;

    float acc = rb2[l] + tb2[l] + fb2[l];
#pragma unroll
    for (int h = 0; h < cH; h++) {
        float hr = fmaf(dist, s_rw1[h], fmaf(st, s_rw1[cH + h], fmaf(ct, s_rw1[2 * cH + h], s_rb1[h])));
        if (hr > 0.f) acc += hr * s_rw2[h];
        float ht = fmaf(dx, s_tw1[h], fmaf(dy, s_tw1[cH + h], s_tb1[h]));
        if (ht > 0.f) acc += ht * s_tw2[h];
        float hf = fmaf(dx, s_fw1[h] - s_fw1[2 * cH + h],
                    fmaf(dy, s_fw1[cH + h] - s_fw1[3 * cH + h], s_fb1[h]));
        if (hf > 0.f) acc += hf * s_fw2[h];
    }
    lut[l * LUTSZ + idx] = acc;
}

// ---------------------------------------------------------------------------
// Warp-per-row softmax / LN / pool / fc (unchanged)
// ---------------------------------------------------------------------------
__global__ __launch_bounds__(256) void softmax_kernel(
    const float* __restrict__ sc, __half* __restrict__ pr)
{
    const int row  = blockIdx.x * 8 + (threadIdx.x >> 5);
    const int lane = threadIdx.x & 31;
    const float4* p = (const float4*)(sc + (size_t)row * cS);
    uint2* ph = (uint2*)(pr + (size_t)row * cS);

    float4 v[8];
    float m = -3.0e38f;
#pragma unroll
    for (int k = 0; k < 8; k++) {
        v[k] = p[lane + k * 32];
        m = fmaxf(m, fmaxf(fmaxf(v[k].x, v[k].y), fmaxf(v[k].z, v[k].w)));
    }
    m = warpMax(m);
    float s = 0.f;
#pragma unroll
    for (int k = 0; k < 8; k++) {
        v[k].x = __expf(v[k].x - m); v[k].y = __expf(v[k].y - m);
        v[k].z = __expf(v[k].z - m); v[k].w = __expf(v[k].w - m);
        s += v[k].x + v[k].y + v[k].z + v[k].w;
    }
    s = warpSum(s);
    const float inv = 1.f / s;
#pragma unroll
    for (int k = 0; k < 8; k++) {
        __half2 h0 = __floats2half2_rn(v[k].x * inv, v[k].y * inv);
        __half2 h1 = __floats2half2_rn(v[k].z * inv, v[k].w * inv);
        uint2 u;
        u.x = *(uint32_t*)&h0; u.y = *(uint32_t*)&h1;
        ph[lane + k * 32] = u;
    }
}

__global__ __launch_bounds__(256) void ln_kernel(
    float* __restrict__ x, __half* __restrict__ xh, const float* __restrict__ add,
    const float* __restrict__ g, const float* __restrict__ b)
{
    const int row  = blockIdx.x * 8 + (threadIdx.x >> 5);
    const int lane = threadIdx.x & 31;
    float4* px = (float4*)(x + (size_t)row * cD);

    float4 v[4];
    float s = 0.f, s2 = 0.f;
#pragma unroll
    for (int k = 0; k < 4; k++) {
        v[k] = px[lane + k * 32];
        if (add) {
            float4 a4 = ((const float4*)(add + (size_t)row * cD))[lane + k * 32];
            v[k].x += a4.x; v[k].y += a4.y; v[k].z += a4.z; v[k].w += a4.w;
        }
        s  += v[k].x + v[k].y + v[k].z + v[k].w;
        s2 += v[k].x * v[k].x + v[k].y * v[k].y + v[k].z * v[k].z + v[k].w * v[k].w;
    }
    s = warpSum(s); s2 = warpSum(s2);
    const float mu = s * (1.f / cD);
    const float var = fmaxf(s2 * (1.f / cD) - mu * mu, 0.f);
    const float rs = rsqrtf(var + 1e-5f);
#pragma unroll
    for (int k = 0; k < 4; k++) {
        const int e = (lane + k * 32) * 4;
        float4 g4 = ((const float4*)g)[lane + k * 32];
        float4 b4 = ((const float4*)b)[lane + k * 32];
        float4 o;
        o.x = (v[k].x - mu) * rs * g4.x + b4.x;
        o.y = (v[k].y - mu) * rs * g4.y + b4.y;
        o.z = (v[k].z - mu) * rs * g4.z + b4.z;
        o.w = (v[k].w - mu) * rs * g4.w + b4.w;
        px[lane + k * 32] = o;
        if (xh) {
            __half2 h0 = __floats2half2_rn(o.x, o.y);
            __half2 h1 = __floats2half2_rn(o.z, o.w);
            uint2 u; u.x = *(uint32_t*)&h0; u.y = *(uint32_t*)&h1;
            *(uint2*)(xh + (size_t)row * cD + e) = u;
        }
    }
}

__global__ __launch_bounds__(256) void pool_kernel(const float* __restrict__ x, float* __restrict__ outp) {
    const int b = blockIdx.y;
    const int s0 = blockIdx.x * 64;
    const int d = threadIdx.x * 2;
    float2 acc = make_float2(0.f, 0.f);
    const float* p = x + ((size_t)b * cS + s0) * cD + d;
#pragma unroll 8
    for (int i = 0; i < 64; i++) {
        float2 val = *(const float2*)(p + (size_t)i * cD);
        acc.x += val.x; acc.y += val.y;
    }
    atomicAdd(&outp[b * cD + d],     acc.x * (1.f / cS));
    atomicAdd(&outp[b * cD + d + 1], acc.y * (1.f / cS));
}

__global__ __launch_bounds__(256) void fc_kernel(
    const float* __restrict__ pooled, const float* __restrict__ w,
    float* __restrict__ outc)
{
    const int idx = blockIdx.x * 256 + threadIdx.x;
    if (idx >= cB * cC) return;
    const int b = idx / cC, c = idx % cC;
    const int d0 = blockIdx.y * 128;
    const float* pp = pooled + b * cD + d0;
    const float* wp = w + (size_t)d0 * cC + c;
    float s = 0.f;
#pragma unroll 8
    for (int d = 0; d < 128; d++) s += pp[d] * wp[(size_t)d * cC];
    atomicAdd(&outc[idx], s);
}

// ---------------------------------------------------------------------------
// Launch
// ---------------------------------------------------------------------------
extern "C" void kernel_launch(void* const* d_in, const int* in_sizes, int n_in,
                              void* d_out, int out_size)
{
    const float* x      = (const float*)d_in[0];
    const float* coords = (const float*)d_in[1];
    const float* Wq     = (const float*)d_in[2];
    const float* Wk     = (const float*)d_in[3];
    const float* Wv     = (const float*)d_in[4];
    const float* rw1 = (const float*)d_in[5],  *rb1 = (const float*)d_in[6];
    const float* rw2 = (const float*)d_in[7],  *rb2 = (const float*)d_in[8];
    const float* tw1 = (const float*)d_in[9],  *tb1 = (const float*)d_in[10];
    const float* tw2 = (const float*)d_in[11], *tb2 = (const float*)d_in[12];
    const float* fw1 = (const float*)d_in[13], *fb1 = (const float*)d_in[14];
    const float* fw2 = (const float*)d_in[15], *fb2 = (const float*)d_in[16];
    const float* ln1g = (const float*)d_in[17], *ln1b = (const float*)d_in[18];
    const float* ffw1 = (const float*)d_in[19], *ffb1 = (const float*)d_in[20];
    const float* ffw2 = (const float*)d_in[21], *ffb2 = (const float*)d_in[22];
    const float* ln2g = (const float*)d_in[23], *ln2b = (const float*)d_in[24];
    const float* lnfg = (const float*)d_in[25], *lnfb = (const float*)d_in[26];
    const float* fcw  = (const float*)d_in[27], *fcb  = (const float*)d_in[28];
    float* out = (float*)d_out;

    float *gx, *gS, *gLut, *gT, *gP;
    __half *gxh, *gQh, *gKh, *gVh, *gPr, *gHh, *gwq, *gwk, *gwv, *gf1, *gf2;
    cudaGetSymbolAddress((void**)&gx,   g_x);
    cudaGetSymbolAddress((void**)&gxh,  g_xh);
    cudaGetSymbolAddress((void**)&gQh,  g_Qh);
    cudaGetSymbolAddress((void**)&gKh,  g_Kh);
    cudaGetSymbolAddress((void**)&gVh,  g_Vh);
    cudaGetSymbolAddress((void**)&gS,   g_scores);
    cudaGetSymbolAddress((void**)&gPr,  g_probs);
    cudaGetSymbolAddress((void**)&gLut, g_blut);
    cudaGetSymbolAddress((void**)&gT,   g_tmp);
    cudaGetSymbolAddress((void**)&gHh,  g_Hh);
    cudaGetSymbolAddress((void**)&gP,   g_pooled);
    cudaGetSymbolAddress((void**)&gwq,  g_wq);
    cudaGetSymbolAddress((void**)&gwk,  g_wk);
    cudaGetSymbolAddress((void**)&gwv,  g_wv);
    cudaGetSymbolAddress((void**)&gf1,  g_f1);
    cudaGetSymbolAddress((void**)&gf2,  g_f2);

    const float invscale = 1.f / sqrtf((float)cD);
    const int BS = cB * cS;  // 2048

    constexpr int smBigNN = hSmemBytes(4, 8, false);  // 128x128 NN: 56832
    constexpr int smNT44  = hSmemBytes(4, 4, true);   // 128x64  NT: 46080
    constexpr int smNN24  = hSmemBytes(2, 4, false);  // 64x64   NN: 29184
    cudaFuncSetAttribute(hgemm_kernel<4, 8, 2, false, 0, true,  true>,  cudaFuncAttributeMaxDynamicSharedMemorySize, smBigNN);
    cudaFuncSetAttribute(hgemm_kernel<4, 4, 3, true,  3, false, false>, cudaFuncAttributeMaxDynamicSharedMemorySize, smNT44);
    cudaFuncSetAttribute(hgemm_kernel<2, 4, 3, false, 0, false, false>, cudaFuncAttributeMaxDynamicSharedMemorySize, smNN24);
    cudaFuncSetAttribute(hgemm_kernel<4, 8, 2, false, 1, true,  false>, cudaFuncAttributeMaxDynamicSharedMemorySize, smBigNN);
    cudaFuncSetAttribute(hgemm_kernel<2, 4, 3, false, 2, false, false>, cudaFuncAttributeMaxDynamicSharedMemorySize, smNN24);

    prep_kernel<<<(S7 + 255) / 256, 256>>>(
        Wq, Wk, Wv, ffw1, ffw2, x, fcb,
        gwq, gwk, gwv, gf1, gf2, gx, gxh, out, gP);

    biaslut_kernel<<<dim3((LUTSZ + 255) / 256, cL), 256>>>(coords,
        rw1, rb1, rw2, rb2, tw1, tb1, tw2, tb2, fw1, fb1, fw2, fb2, gLut);

    for (int l = 0; l < cL; l++) {
        const size_t wo = (size_t)l * cD * cD;
        // Fused QKV: 128x128 tiles (big warp tile) -> grid 12x16 = 192 CTAs
        hgemm_kernel<4, 8, 2, false, 0, true, true><<<dim3(3 * (cD / 128), BS / 128), 128, smBigNN>>>(
            gxh, gwq + wo, gQh, gwk + wo, gKh, gwv + wo, gVh,
            BS, cD, cD, 0, 0, 0, cD / 128, nullptr, nullptr, 0.f);

        // scores: 128x64 tiles (R13) -> grid 16x8x2 = 256 CTAs
        hgemm_kernel<4, 4, 3, true, 3, false, false><<<dim3(cS / 64, cS / 128, cB), 128, smNT44>>>(
            gQh, gKh, gS, nullptr, nullptr, nullptr, nullptr,
            cS, cS, cD, cS * cD, cS * cD, cS * cS, 0,
            nullptr, gLut + (size_t)l * LUTSZ, invscale);

        softmax_kernel<<<BS / 8, 256>>>(gS, gPr);

        // attn_out: 64x64 tiles (R13) -> grid 8x16x2 = 256 CTAs
        hgemm_kernel<2, 4, 3, false, 0, false, false><<<dim3(cD / 64, cS / 64, cB), 128, smNN24>>>(
            gPr, gVh, gT, nullptr, nullptr, nullptr, nullptr,
            cS, cD, cS, cS * cS, cS * cD, cS * cD, 0, nullptr, nullptr, 0.f);

        ln_kernel<<<BS / 8, 256>>>(gx, gxh, gT, ln1g + l * cD, ln1b + l * cD);

        // FFN1: 128x128 tiles (big warp tile) -> grid 16x16 = 256 CTAs
        hgemm_kernel<4, 8, 2, false, 1, true, false><<<dim3(cF / 128, BS / 128), 128, smBigNN>>>(
            gxh, gf1 + (size_t)l * cD * cF, gHh, nullptr, nullptr, nullptr, nullptr,
            BS, cF, cD, 0, 0, 0, 0, ffb1 + l * cF, nullptr, 0.f);
        // FFN2: 64x64 tiles (R13) -> grid 8x32 = 256 CTAs
        hgemm_kernel<2, 4, 3, false, 2, false, false><<<dim3(cD / 64, BS / 64), 128, smNN24>>>(
            gHh, gf2 + (size_t)l * cF * cD, gT, nullptr, nullptr, nullptr, nullptr,
            BS, cD, cF, 0, 0, 0, 0, ffb2 + l * cD, nullptr, 0.f);

        ln_kernel<<<BS / 8, 256>>>(gx, gxh, gT, ln2g + l * cD, ln2b + l * cD);
    }

    ln_kernel<<<BS / 8, 256>>>(gx, nullptr, nullptr, lnfg, lnfb);
    pool_kernel<<<dim3(cS / 64, cB), 256>>>(gx, gP);
    fc_kernel<<<dim3((cB * cC + 255) / 256, cD / 128), 256>>>(gP, fcw, out);
}

// round 16
// speedup vs baseline: 1.1104x; 1.0483x over previous
#include <cuda_runtime.h>
#include <cuda_fp16.h>
#include <math.h>
#include <stdint.h>

constexpr int cB = 2, cS = 1024, cD = 512, cH = 32, cF = 2048, cC = 1000, cL = 2;
constexpr int LUTN = 63, LUTSZ = LUTN * LUTN;

// ---------------------------------------------------------------------------
// Scratch
// ---------------------------------------------------------------------------
__device__ float  g_x[cB * cS * cD];
__device__ __half g_xh[cB * cS * cD];
__device__ __half g_Qh[cB * cS * cD];
__device__ __half g_Kh[cB * cS * cD];
__device__ __half g_Vh[cB * cS * cD];
__device__ float  g_scores[cB * cS * cS];
__device__ __half g_probs[cB * cS * cS];
__device__ float  g_blut[cL * LUTSZ];
__device__ float  g_tmp[cB * cS * cD];
__device__ __half g_Hh[cB * cS * cF];
__device__ float  g_pooled[cB * cD];
__device__ __half g_wq[cL * cD * cD];
__device__ __half g_wk[cL * cD * cD];
__device__ __half g_wv[cL * cD * cD];
__device__ __half g_f1[cL * cD * cF];
__device__ __half g_f2[cL * cF * cD];

// ---------------------------------------------------------------------------
// Reductions
// ---------------------------------------------------------------------------
__device__ __forceinline__ float warpSum(float v) {
#pragma unroll
    for (int o = 16; o > 0; o >>= 1) v += __shfl_xor_sync(0xffffffffu, v, o);
    return v;
}
__device__ __forceinline__ float warpMax(float v) {
#pragma unroll
    for (int o = 16; o > 0; o >>= 1) v = fmaxf(v, __shfl_xor_sync(0xffffffffu, v, o));
    return v;
}

// ---------------------------------------------------------------------------
// fp16 GEMM, m16n8k16, fp32 accumulate. 128 threads (4 warps, 2x2 warp grid).
// CTA tile (32*MT) x (16*WNT); warp tile (16*MT) x (8*WNT).
// TBK=64 (R15 finding: tensor% invariant to warps/tile-area -> binding cost
// is the per-iteration sync/ramp overhead; doubling K-depth per iteration
// halves iterations so overhead amortizes over 2x MMA work).
// Smem rows: 64 halfs + 8 pad -> stride 72 halfs (144B); row bank step
// 36 words = 4 mod 32 -> ldmatrix 8-row phases conflict-free, as before.
// MAXB: blocks/SM for launch_bounds.
// NT=true : B is [N, K] row-major, non-trans ldmatrix.
// NT=false: B is [K, N] row-major, ldmatrix.trans.
// EPI: 0 plain | 1 +bias+relu | 2 +bias | 3 *scale + LUT-bias (scores)
// OUTH: half output. FUSE3: QKV sharing A. Batched via grid.z strides.
// ---------------------------------------------------------------------------
constexpr int TBK  = 64;   // halfs per k-tile
constexpr int HSTR = 72;   // A / NT-B smem row stride (halfs) = 144 B
constexpr int STG  = 3;

__device__ __forceinline__ void cpa16(uint32_t dst, const void* src) {
    asm volatile("cp.async.cg.shared.global [%0], [%1], 16;\n" :: "r"(dst), "l"(src));
}
__device__ __forceinline__ void ldm4(uint32_t addr, uint32_t& r0, uint32_t& r1,
                                     uint32_t& r2, uint32_t& r3) {
    asm volatile("ldmatrix.sync.aligned.m8n8.x4.shared.b16 {%0,%1,%2,%3}, [%4];"
                 : "=r"(r0), "=r"(r1), "=r"(r2), "=r"(r3) : "r"(addr));
}
__device__ __forceinline__ void ldm4t(uint32_t addr, uint32_t& r0, uint32_t& r1,
                                      uint32_t& r2, uint32_t& r3) {
    asm volatile("ldmatrix.sync.aligned.m8n8.x4.trans.shared.b16 {%0,%1,%2,%3}, [%4];"
                 : "=r"(r0), "=r"(r1), "=r"(r2), "=r"(r3) : "r"(addr));
}
__device__ __forceinline__ void mma_f16(float c[4], const uint32_t a[4], const uint32_t b[2]) {
    asm volatile(
        "mma.sync.aligned.m16n8k16.row.col.f32.f16.f16.f32 "
        "{%0,%1,%2,%3}, {%4,%5,%6,%7}, {%8,%9}, {%0,%1,%2,%3};"
        : "+f"(c[0]), "+f"(c[1]), "+f"(c[2]), "+f"(c[3])
        : "r"(a[0]), "r"(a[1]), "r"(a[2]), "r"(a[3]), "r"(b[0]), "r"(b[1]));
}

constexpr int hSmemBytes(int MT, int WNT, bool NT) {
    const int TN = 16 * WNT;
    const int ab = (32 * MT) * HSTR * 2;
    const int bb = NT ? TN * HSTR * 2 : TBK * (TN + 8) * 2;
    return STG * (ab + bb);
}

template <int MT, int WNT, int MAXB, bool NT, int EPI, bool OUTH, bool FUSE3>
__global__ __launch_bounds__(128, MAXB) void hgemm_kernel(
    const __half* __restrict__ A, const __half* __restrict__ Bm, void* Cm_,
    const __half* __restrict__ B1, void* C1_,
    const __half* __restrict__ B2, void* C2_,
    int M, int N, int K, int sA, int sB, int sC, int nb,
    const float* __restrict__ biasv, const float* __restrict__ lutOrBias, float scalev)
{
    constexpr int TM = 32 * MT;
    constexpr int TN = 16 * WNT;
    constexpr int BSTRh = NT ? HSTR : (TN + 8);
    constexpr int ABYTES = TM * HSTR * 2;
    constexpr int BBYTES = NT ? TN * HSTR * 2 : TBK * BSTRh * 2;

    extern __shared__ __half smem[];
    const uint32_t sbase = (uint32_t)__cvta_generic_to_shared(smem);
    const uint32_t aBase = sbase;
    const uint32_t bBase = sbase + STG * ABYTES;

    A  += (size_t)blockIdx.z * sA;
    Bm += (size_t)blockIdx.z * sB;
    char* Cme = (char*)Cm_ + (size_t)blockIdx.z * sC * (OUTH ? 2 : 4);

    int bx = blockIdx.x;
    if (FUSE3) {
        const int mat = bx / nb;
        bx -= mat * nb;
        if (mat == 1) { Bm = B1; Cme = (char*)C1_; }
        else if (mat == 2) { Bm = B2; Cme = (char*)C2_; }
    }
    const int bm0 = blockIdx.y * TM;
    const int bn0 = bx * TN;

    const int t = threadIdx.x;
    const int lane = t & 31, w = t >> 5;
    const int gid = lane >> 2, tidg = lane & 3;
    const int wm0 = (w & 1) * (16 * MT);
    const int wn0 = (w >> 1) * (8 * WNT);

    const int aRow = (lane & 15);
    const int aKB  = ((lane >> 4) & 1) * 16;
    const int bRow = (lane & 7) + ((lane >> 4) & 1) * 8;
    const int bKB  = ((lane >> 3) & 1) * 16;
    const int bRowT = ((lane >> 3) & 1) * 8 + (lane & 7);
    const int bColT = (lane >> 4) * 8;

    auto load_stage = [&](int st, int k0) {
        const uint32_t ab = aBase + st * ABYTES;
#pragma unroll
        for (int i = 0; i < (TM * 8) / 128; i++) {   // TM rows x 8 chunks
            const int idx = t + i * 128;
            const int row = idx >> 3, c16 = idx & 7;
            cpa16(ab + row * (HSTR * 2) + c16 * 16, A + (size_t)(bm0 + row) * K + k0 + c16 * 8);
        }
        const uint32_t bb = bBase + st * BBYTES;
        if (NT) {
#pragma unroll
            for (int i = 0; i < (TN * 8) / 128; i++) {
                const int idx = t + i * 128;
                const int row = idx >> 3, c16 = idx & 7;
                cpa16(bb + row * (HSTR * 2) + c16 * 16, Bm + (size_t)(bn0 + row) * K + k0 + c16 * 8);
            }
        } else {
            constexpr int perRow = TN / 8;
#pragma unroll
            for (int i = 0; i < (TBK * perRow) / 128; i++) {
                const int idx = t + i * 128;
                const int kk = idx / perRow, ch = idx % perRow;
                cpa16(bb + kk * (BSTRh * 2) + ch * 16, Bm + (size_t)(k0 + kk) * N + bn0 + ch * 8);
            }
        }
    };

    float acc[MT][WNT][4] = {};
    const int nk = K / TBK;   // >= 8 at every call site

    load_stage(0, 0);
    asm volatile("cp.async.commit_group;" ::: "memory");
    load_stage(1, TBK);
    asm volatile("cp.async.commit_group;" ::: "memory");

    for (int it = 0; it < nk; it++) {
        asm volatile("cp.async.wait_group 1;" ::: "memory");
        __syncthreads();
        const int nxt = it + 2;
        if (nxt < nk) load_stage(nxt % STG, nxt * TBK);
        asm volatile("cp.async.commit_group;" ::: "memory");

        const int st = it % STG;
        const uint32_t aLane = aBase + st * ABYTES + (wm0 + aRow) * (HSTR * 2) + aKB;
        const uint32_t bST   = bBase + st * BBYTES;

#pragma unroll
        for (int ks = 0; ks < 4; ks++) {
            uint32_t a[MT][4], b[WNT][2];
#pragma unroll
            for (int mt = 0; mt < MT; mt++)
                ldm4(aLane + mt * (16 * HSTR * 2) + ks * 32,
                     a[mt][0], a[mt][1], a[mt][2], a[mt][3]);
#pragma unroll
            for (int np = 0; np < WNT / 2; np++) {
                uint32_t r0, r1, r2, r3;
                if (NT) {
                    const uint32_t addr = bST + (wn0 + np * 16 + bRow) * (HSTR * 2) + ks * 32 + bKB;
                    ldm4(addr, r0, r1, r2, r3);
                } else {
                    const uint32_t addr = bST + (ks * 16 + bRowT) * (BSTRh * 2)
                                        + (wn0 + np * 16 + bColT) * 2;
                    ldm4t(addr, r0, r1, r2, r3);
                }
                b[2 * np][0] = r0; b[2 * np][1] = r1;
                b[2 * np + 1][0] = r2; b[2 * np + 1][1] = r3;
            }
#pragma unroll
            for (int mt = 0; mt < MT; mt++)
#pragma unroll
                for (int nt = 0; nt < WNT; nt++)
                    mma_f16(acc[mt][nt], a[mt], b[nt]);
        }
    }

#pragma unroll
    for (int mt = 0; mt < MT; mt++) {
#pragma unroll
        for (int nt = 0; nt < WNT; nt++) {
            const int row = bm0 + wm0 + mt * 16 + gid;
            const int col = bn0 + wn0 + nt * 8 + tidg * 2;
#pragma unroll
            for (int h = 0; h < 2; h++) {
                const int r = row + h * 8;
                float vx = acc[mt][nt][h * 2], vy = acc[mt][nt][h * 2 + 1];
                if (EPI == 1 || EPI == 2) {
                    vx += biasv[col]; vy += biasv[col + 1];
                    if (EPI == 1) { vx = fmaxf(vx, 0.f); vy = fmaxf(vy, 0.f); }
                }
                if (EPI == 3) {
                    const int ix = r >> 5, iy = r & 31;
                    const int a0 = ((col)     >> 5) - ix + 31, b0 = ((col)     & 31) - iy + 31;
                    const int a1 = ((col + 1) >> 5) - ix + 31, b1 = ((col + 1) & 31) - iy + 31;
                    vx = vx * scalev + __ldg(lutOrBias + a0 * LUTN + b0);
                    vy = vy * scalev + __ldg(lutOrBias + a1 * LUTN + b1);
                }
                if (OUTH) {
                    *(__half2*)((__half*)Cme + (size_t)r * N + col) = __floats2half2_rn(vx, vy);
                } else {
                    *(float2*)((float*)Cme + (size_t)r * N + col) = make_float2(vx, vy);
                }
            }
        }
    }
}

// ---------------------------------------------------------------------------
// Fused prep (unchanged)
// ---------------------------------------------------------------------------
constexpr int N1 = cL * cD * cD / 4;
constexpr int N2 = cL * cD * cF / 4;
constexpr int NX = cB * cS * cD / 4;
constexpr int NO = (cB * cC) / 4;
constexpr int NP = (cB * cD) / 4;
constexpr int S0 = N1, S1 = 2 * N1, S2 = 3 * N1;
constexpr int S3 = S2 + N2, S4 = S3 + N2, S5 = S4 + NX, S6 = S5 + NO, S7 = S6 + NP;

__device__ __forceinline__ void cvt4(const float* s, __half* d, int i) {
    float4 v = ((const float4*)s)[i];
    ((__half2*)d)[2 * i]     = __floats2half2_rn(v.x, v.y);
    ((__half2*)d)[2 * i + 1] = __floats2half2_rn(v.z, v.w);
}

__global__ __launch_bounds__(256) void prep_kernel(
    const float* __restrict__ Wq, const float* __restrict__ Wk, const float* __restrict__ Wv,
    const float* __restrict__ f1, const float* __restrict__ f2,
    const float* __restrict__ x,  const float* __restrict__ fcb,
    __half* gwq, __half* gwk, __half* gwv, __half* gf1, __half* gf2,
    float* gx, __half* gxh, float* outp, float* pooled)
{
    const int i = blockIdx.x * 256 + threadIdx.x;
    if (i < S0)      cvt4(Wq, gwq, i);
    else if (i < S1) cvt4(Wk, gwk, i - S0);
    else if (i < S2) cvt4(Wv, gwv, i - S1);
    else if (i < S3) cvt4(f1, gf1, i - S2);
    else if (i < S4) cvt4(f2, gf2, i - S3);
    else if (i < S5) {
        const int j = i - S4;
        float4 v = ((const float4*)x)[j];
        ((float4*)gx)[j] = v;
        ((__half2*)gxh)[2 * j]     = __floats2half2_rn(v.x, v.y);
        ((__half2*)gxh)[2 * j + 1] = __floats2half2_rn(v.z, v.w);
    } else if (i < S6) {
        const int j = i - S5;
#pragma unroll
        for (int q = 0; q < 4; q++) {
            const int e = j * 4 + q;
            outp[e] = fcb[e % cC];
        }
    } else if (i < S7) {
        ((float4*)pooled)[i - S6] = make_float4(0.f, 0.f, 0.f, 0.f);
    }
}

// ---------------------------------------------------------------------------
// Pair-bias LUT (unchanged)
// ---------------------------------------------------------------------------
__global__ __launch_bounds__(256) void biaslut_kernel(
    const float* __restrict__ coords,
    const float* __restrict__ rw1, const float* __restrict__ rb1,
    const float* __restrict__ rw2, const float* __restrict__ rb2,
    const float* __restrict__ tw1, const float* __restrict__ tb1,
    const float* __restrict__ tw2, const float* __restrict__ tb2,
    const float* __restrict__ fw1, const float* __restrict__ fb1,
    const float* __restrict__ fw2, const float* __restrict__ fb2,
    float* __restrict__ lut)
{
    const int l = blockIdx.y;
    __shared__ float s_rw1[3 * cH], s_rb1[cH], s_rw2[cH];
    __shared__ float s_tw1[2 * cH], s_tb1[cH], s_tw2[cH];
    __shared__ float s_fw1[4 * cH], s_fb1[cH], s_fw2[cH];
    const int t = threadIdx.x;
    if (t < 3 * cH) s_rw1[t] = rw1[l * 3 * cH + t];
    if (t < 2 * cH) s_tw1[t] = tw1[l * 2 * cH + t];
    if (t < 4 * cH) s_fw1[t] = fw1[l * 4 * cH + t];
    if (t < cH) {
        s_rb1[t] = rb1[l * cH + t]; s_rw2[t] = rw2[l * cH + t];
        s_tb1[t] = tb1[l * cH + t]; s_tw2[t] = tw2[l * cH + t];
        s_fb1[t] = fb1[l * cH + t]; s_fw2[t] = fw2[l * cH + t];
    }
    __syncthreads();

    const int idx = blockIdx.x * 256 + t;
    if (idx >= LUTSZ) return;
    const int da = idx / LUTN - 31;
    const int db = idx % LUTN - 31;
    const float xa = coords[2 * (da < 0 ? -da : da) + 1];
    const float xb = coords[2 * (db < 0 ? -db : db) + 1];
    const float dx = (da < 0) ? -xa : xa;
    const float dy = (db < 0) ? -xb : xb;

    const float r2 = dx * dx + dy * dy;
    const float dist = sqrtf(r2 + 1e-8f);
    const float rinv = (r2 > 0.f) ? rsqrtf(r2) : 0.f;
    const float st = dy * rinv;
    const float ct = (r2 > 0.f) ? dx * rinv : 1.f;

    float acc = rb2[l] + tb2[l] + fb2[l];
#pragma unroll
    for (int h = 0; h < cH; h++) {
        float hr = fmaf(dist, s_rw1[h], fmaf(st, s_rw1[cH + h], fmaf(ct, s_rw1[2 * cH + h], s_rb1[h])));
        if (hr > 0.f) acc += hr * s_rw2[h];
        float ht = fmaf(dx, s_tw1[h], fmaf(dy, s_tw1[cH + h], s_tb1[h]));
        if (ht > 0.f) acc += ht * s_tw2[h];
        float hf = fmaf(dx, s_fw1[h] - s_fw1[2 * cH + h],
                    fmaf(dy, s_fw1[cH + h] - s_fw1[3 * cH + h], s_fb1[h]));
        if (hf > 0.f) acc += hf * s_fw2[h];
    }
    lut[l * LUTSZ + idx] = acc;
}

// ---------------------------------------------------------------------------
// Warp-per-row softmax / LN / pool / fc (unchanged)
// ---------------------------------------------------------------------------
__global__ __launch_bounds__(256) void softmax_kernel(
    const float* __restrict__ sc, __half* __restrict__ pr)
{
    const int row  = blockIdx.x * 8 + (threadIdx.x >> 5);
    const int lane = threadIdx.x & 31;
    const float4* p = (const float4*)(sc + (size_t)row * cS);
    uint2* ph = (uint2*)(pr + (size_t)row * cS);

    float4 v[8];
    float m = -3.0e38f;
#pragma unroll
    for (int k = 0; k < 8; k++) {
        v[k] = p[lane + k * 32];
        m = fmaxf(m, fmaxf(fmaxf(v[k].x, v[k].y), fmaxf(v[k].z, v[k].w)));
    }
    m = warpMax(m);
    float s = 0.f;
#pragma unroll
    for (int k = 0; k < 8; k++) {
        v[k].x = __expf(v[k].x - m); v[k].y = __expf(v[k].y - m);
        v[k].z = __expf(v[k].z - m); v[k].w = __expf(v[k].w - m);
        s += v[k].x + v[k].y + v[k].z + v[k].w;
    }
    s = warpSum(s);
    const float inv = 1.f / s;
#pragma unroll
    for (int k = 0; k < 8; k++) {
        __half2 h0 = __floats2half2_rn(v[k].x * inv, v[k].y * inv);
        __half2 h1 = __floats2half2_rn(v[k].z * inv, v[k].w * inv);
        uint2 u;
        u.x = *(uint32_t*)&h0; u.y = *(uint32_t*)&h1;
        ph[lane + k * 32] = u;
    }
}

__global__ __launch_bounds__(256) void ln_kernel(
    float* __restrict__ x, __half* __restrict__ xh, const float* __restrict__ add,
    const float* __restrict__ g, const float* __restrict__ b)
{
    const int row  = blockIdx.x * 8 + (threadIdx.x >> 5);
    const int lane = threadIdx.x & 31;
    float4* px = (float4*)(x + (size_t)row * cD);

    float4 v[4];
    float s = 0.f, s2 = 0.f;
#pragma unroll
    for (int k = 0; k < 4; k++) {
        v[k] = px[lane + k * 32];
        if (add) {
            float4 a4 = ((const float4*)(add + (size_t)row * cD))[lane + k * 32];
            v[k].x += a4.x; v[k].y += a4.y; v[k].z += a4.z; v[k].w += a4.w;
        }
        s  += v[k].x + v[k].y + v[k].z + v[k].w;
        s2 += v[k].x * v[k].x + v[k].y * v[k].y + v[k].z * v[k].z + v[k].w * v[k].w;
    }
    s = warpSum(s); s2 = warpSum(s2);
    const float mu = s * (1.f / cD);
    const float var = fmaxf(s2 * (1.f / cD) - mu * mu, 0.f);
    const float rs = rsqrtf(var + 1e-5f);
#pragma unroll
    for (int k = 0; k < 4; k++) {
        const int e = (lane + k * 32) * 4;
        float4 g4 = ((const float4*)g)[lane + k * 32];
        float4 b4 = ((const float4*)b)[lane + k * 32];
        float4 o;
        o.x = (v[k].x - mu) * rs * g4.x + b4.x;
        o.y = (v[k].y - mu) * rs * g4.y + b4.y;
        o.z = (v[k].z - mu) * rs * g4.z + b4.z;
        o.w = (v[k].w - mu) * rs * g4.w + b4.w;
        px[lane + k * 32] = o;
        if (xh) {
            __half2 h0 = __floats2half2_rn(o.x, o.y);
            __half2 h1 = __floats2half2_rn(o.z, o.w);
            uint2 u; u.x = *(uint32_t*)&h0; u.y = *(uint32_t*)&h1;
            *(uint2*)(xh + (size_t)row * cD + e) = u;
        }
    }
}

__global__ __launch_bounds__(256) void pool_kernel(const float* __restrict__ x, float* __restrict__ outp) {
    const int b = blockIdx.y;
    const int s0 = blockIdx.x * 64;
    const int d = threadIdx.x * 2;
    float2 acc = make_float2(0.f, 0.f);
    const float* p = x + ((size_t)b * cS + s0) * cD + d;
#pragma unroll 8
    for (int i = 0; i < 64; i++) {
        float2 val = *(const float2*)(p + (size_t)i * cD);
        acc.x += val.x; acc.y += val.y;
    }
    atomicAdd(&outp[b * cD + d],     acc.x * (1.f / cS));
    atomicAdd(&outp[b * cD + d + 1], acc.y * (1.f / cS));
}

__global__ __launch_bounds__(256) void fc_kernel(
    const float* __restrict__ pooled, const float* __restrict__ w,
    float* __restrict__ outc)
{
    const int idx = blockIdx.x * 256 + threadIdx.x;
    if (idx >= cB * cC) return;
    const int b = idx / cC, c = idx % cC;
    const int d0 = blockIdx.y * 128;
    const float* pp = pooled + b * cD + d0;
    const float* wp = w + (size_t)d0 * cC + c;
    float s = 0.f;
#pragma unroll 8
    for (int d = 0; d < 128; d++) s += pp[d] * wp[(size_t)d * cC];
    atomicAdd(&outc[idx], s);
}

// ---------------------------------------------------------------------------
// Launch
// ---------------------------------------------------------------------------
extern "C" void kernel_launch(void* const* d_in, const int* in_sizes, int n_in,
                              void* d_out, int out_size)
{
    const float* x      = (const float*)d_in[0];
    const float* coords = (const float*)d_in[1];
    const float* Wq     = (const float*)d_in[2];
    const float* Wk     = (const float*)d_in[3];
    const float* Wv     = (const float*)d_in[4];
    const float* rw1 = (const float*)d_in[5],  *rb1 = (const float*)d_in[6];
    const float* rw2 = (const float*)d_in[7],  *rb2 = (const float*)d_in[8];
    const float* tw1 = (const float*)d_in[9],  *tb1 = (const float*)d_in[10];
    const float* tw2 = (const float*)d_in[11], *tb2 = (const float*)d_in[12];
    const float* fw1 = (const float*)d_in[13], *fb1 = (const float*)d_in[14];
    const float* fw2 = (const float*)d_in[15], *fb2 = (const float*)d_in[16];
    const float* ln1g = (const float*)d_in[17], *ln1b = (const float*)d_in[18];
    const float* ffw1 = (const float*)d_in[19], *ffb1 = (const float*)d_in[20];
    const float* ffw2 = (const float*)d_in[21], *ffb2 = (const float*)d_in[22];
    const float* ln2g = (const float*)d_in[23], *ln2b = (const float*)d_in[24];
    const float* lnfg = (const float*)d_in[25], *lnfb = (const float*)d_in[26];
    const float* fcw  = (const float*)d_in[27], *fcb  = (const float*)d_in[28];
    float* out = (float*)d_out;

    float *gx, *gS, *gLut, *gT, *gP;
    __half *gxh, *gQh, *gKh, *gVh, *gPr, *gHh, *gwq, *gwk, *gwv, *gf1, *gf2;
    cudaGetSymbolAddress((void**)&gx,   g_x);
    cudaGetSymbolAddress((void**)&gxh,  g_xh);
    cudaGetSymbolAddress((void**)&gQh,  g_Qh);
    cudaGetSymbolAddress((void**)&gKh,  g_Kh);
    cudaGetSymbolAddress((void**)&gVh,  g_Vh);
    cudaGetSymbolAddress((void**)&gS,   g_scores);
    cudaGetSymbolAddress((void**)&gPr,  g_probs);
    cudaGetSymbolAddress((void**)&gLut, g_blut);
    cudaGetSymbolAddress((void**)&gT,   g_tmp);
    cudaGetSymbolAddress((void**)&gHh,  g_Hh);
    cudaGetSymbolAddress((void**)&gP,   g_pooled);
    cudaGetSymbolAddress((void**)&gwq,  g_wq);
    cudaGetSymbolAddress((void**)&gwk,  g_wk);
    cudaGetSymbolAddress((void**)&gwv,  g_wv);
    cudaGetSymbolAddress((void**)&gf1,  g_f1);
    cudaGetSymbolAddress((void**)&gf2,  g_f2);

    const float invscale = 1.f / sqrtf((float)cD);
    const int BS = cB * cS;  // 2048

    constexpr int smNT44 = hSmemBytes(4, 4, true);   // 128x64 NT: 82944
    constexpr int smNN44 = hSmemBytes(4, 4, false);  // 128x64 NN: 82944
    constexpr int smNN24 = hSmemBytes(2, 4, false);  // 64x64  NN: 55296
    cudaFuncSetAttribute(hgemm_kernel<4, 4, 2, false, 0, true,  true>,  cudaFuncAttributeMaxDynamicSharedMemorySize, smNN44);
    cudaFuncSetAttribute(hgemm_kernel<4, 4, 2, true,  3, false, false>, cudaFuncAttributeMaxDynamicSharedMemorySize, smNT44);
    cudaFuncSetAttribute(hgemm_kernel<2, 4, 3, false, 0, false, false>, cudaFuncAttributeMaxDynamicSharedMemorySize, smNN24);
    cudaFuncSetAttribute(hgemm_kernel<4, 4, 2, false, 1, true,  false>, cudaFuncAttributeMaxDynamicSharedMemorySize, smNN44);
    cudaFuncSetAttribute(hgemm_kernel<2, 4, 3, false, 2, false, false>, cudaFuncAttributeMaxDynamicSharedMemorySize, smNN24);

    prep_kernel<<<(S7 + 255) / 256, 256>>>(
        Wq, Wk, Wv, ffw1, ffw2, x, fcb,
        gwq, gwk, gwv, gf1, gf2, gx, gxh, out, gP);

    biaslut_kernel<<<dim3((LUTSZ + 255) / 256, cL), 256>>>(coords,
        rw1, rb1, rw2, rb2, tw1, tb1, tw2, tb2, fw1, fb1, fw2, fb2, gLut);

    for (int l = 0; l < cL; l++) {
        const size_t wo = (size_t)l * cD * cD;
        // Fused QKV: 128x64 tiles -> grid 24x16 = 384 CTAs, nk = 8
        hgemm_kernel<4, 4, 2, false, 0, true, true><<<dim3(3 * (cD / 64), BS / 128), 128, smNN44>>>(
            gxh, gwq + wo, gQh, gwk + wo, gKh, gwv + wo, gVh,
            BS, cD, cD, 0, 0, 0, cD / 64, nullptr, nullptr, 0.f);

        // scores: 128x64 tiles -> grid 16x8x2 = 256 CTAs, nk = 8
        hgemm_kernel<4, 4, 2, true, 3, false, false><<<dim3(cS / 64, cS / 128, cB), 128, smNT44>>>(
            gQh, gKh, gS, nullptr, nullptr, nullptr, nullptr,
            cS, cS, cD, cS * cD, cS * cD, cS * cS, 0,
            nullptr, gLut + (size_t)l * LUTSZ, invscale);

        softmax_kernel<<<BS / 8, 256>>>(gS, gPr);

        // attn_out: 64x64 tiles -> grid 8x16x2 = 256 CTAs, nk = 16
        hgemm_kernel<2, 4, 3, false, 0, false, false><<<dim3(cD / 64, cS / 64, cB), 128, smNN24>>>(
            gPr, gVh, gT, nullptr, nullptr, nullptr, nullptr,
            cS, cD, cS, cS * cS, cS * cD, cS * cD, 0, nullptr, nullptr, 0.f);

        ln_kernel<<<BS / 8, 256>>>(gx, gxh, gT, ln1g + l * cD, ln1b + l * cD);

        // FFN1: 128x64 tiles -> grid 32x16 = 512 CTAs, nk = 8
        hgemm_kernel<4, 4, 2, false, 1, true, false><<<dim3(cF / 64, BS / 128), 128, smNN44>>>(
            gxh, gf1 + (size_t)l * cD * cF, gHh, nullptr, nullptr, nullptr, nullptr,
            BS, cF, cD, 0, 0, 0, 0, ffb1 + l * cF, nullptr, 0.f);
        // FFN2: 64x64 tiles -> grid 8x32 = 256 CTAs, nk = 32
        hgemm_kernel<2, 4, 3, false, 2, false, false><<<dim3(cD / 64, BS / 64), 128, smNN24>>>(
            gHh, gf2 + (size_t)l * cF * cD, gT, nullptr, nullptr, nullptr, nullptr,
            BS, cD, cF, 0, 0, 0, 0, ffb2 + l * cD, nullptr, 0.f);

        ln_kernel<<<BS / 8, 256>>>(gx, gxh, gT, ln2g + l * cD, ln2b + l * cD);
    }

    ln_kernel<<<BS / 8, 256>>>(gx, nullptr, nullptr, lnfg, lnfb);
    pool_kernel<<<dim3(cS / 64, cB), 256>>>(gx, gP);
    fc_kernel<<<dim3((cB * cC + 255) / 256, cD / 128), 256>>>(gP, fcw, out);
}